// round 1
// baseline (speedup 1.0000x reference)
#include <cuda_runtime.h>
#include <math.h>

// Problem constants
#define BSZ 2
#define TT 2048
#define DM 1024
#define DI 2048
#define NH 8
#define DS 64
#define DH 256
#define NROWS (BSZ*TT)          // 4096
#define EPSV 1e-6f

// ---------------- scratch (device globals; no allocation allowed) ----------
__device__ float g_xn[(size_t)NROWS * DM];        // 16 MB
__device__ float g_xz[(size_t)NROWS * 2 * DI];    // 64 MB  (x_ssm_raw | z)
__device__ float g_xs[(size_t)NROWS * DI];        // 32 MB  post conv+silu
__device__ float g_dt[(size_t)NROWS * NH];
__device__ float g_Bm[(size_t)NROWS * NH * DS];   // 8 MB
__device__ float g_Cm[(size_t)NROWS * NH * DS];   // 8 MB
__device__ float g_y [(size_t)NROWS * DI];        // 32 MB  gated y

// ---------------- RMSNorm ---------------------------------------------------
__global__ void rmsnorm_k(const float* __restrict__ x, const float* __restrict__ w)
{
    int row = blockIdx.x;
    const float* xr = x + (size_t)row * DM;
    float s = 0.f;
    for (int i = threadIdx.x; i < DM; i += 256) { float v = xr[i]; s += v * v; }
    __shared__ float red[8];
    #pragma unroll
    for (int o = 16; o; o >>= 1) s += __shfl_xor_sync(0xffffffffu, s, o);
    if ((threadIdx.x & 31) == 0) red[threadIdx.x >> 5] = s;
    __syncthreads();
    if (threadIdx.x < 8) {
        float v = red[threadIdx.x];
        #pragma unroll
        for (int o = 4; o; o >>= 1) v += __shfl_xor_sync(0xffu, v, o);
        if (threadIdx.x == 0) red[0] = rsqrtf(v / (float)DM + EPSV);
    }
    __syncthreads();
    float sc = red[0];
    for (int i = threadIdx.x; i < DM; i += 256)
        g_xn[(size_t)row * DM + i] = xr[i] * sc * w[i];
}

// ---------------- fp32 SGEMM: C[M,N] = A[M,K] @ W[N,K]^T (+Res) -------------
// BM=BN=128, BK=8, 256 threads, 8x8 per-thread microtile.
// Requires M%128==0, N%128==0, K%8==0 (true for all calls here).
template <bool ADD_RES>
__global__ void __launch_bounds__(256)
sgemm_nt(const float* __restrict__ A, const float* __restrict__ W,
         float* __restrict__ C, const float* __restrict__ Res,
         int M, int N, int K)
{
    const int BM = 128, BN = 128, BK = 8, TM = 8, TN = 8;
    __shared__ float As[BK][BM];
    __shared__ float Ws[BK][BN];

    int tid = threadIdx.x;
    int m0 = blockIdx.y * BM;
    int n0 = blockIdx.x * BN;

    int lr = tid >> 1;            // 0..127
    int lc = (tid & 1) * 4;       // 0 or 4
    int tx = tid & 15;            // 0..15 -> n
    int ty = tid >> 4;            // 0..15 -> m

    const float* Aptr = A + (size_t)(m0 + lr) * K + lc;
    const float* Wptr = W + (size_t)(n0 + lr) * K + lc;

    float acc[TM][TN];
    #pragma unroll
    for (int i = 0; i < TM; i++)
        #pragma unroll
        for (int j = 0; j < TN; j++) acc[i][j] = 0.f;

    for (int k0 = 0; k0 < K; k0 += BK) {
        float4 a4 = *(const float4*)(Aptr + k0);
        float4 w4 = *(const float4*)(Wptr + k0);
        __syncthreads();
        As[lc + 0][lr] = a4.x; As[lc + 1][lr] = a4.y;
        As[lc + 2][lr] = a4.z; As[lc + 3][lr] = a4.w;
        Ws[lc + 0][lr] = w4.x; Ws[lc + 1][lr] = w4.y;
        Ws[lc + 2][lr] = w4.z; Ws[lc + 3][lr] = w4.w;
        __syncthreads();
        #pragma unroll
        for (int kk = 0; kk < BK; kk++) {
            float a[TM], b[TN];
            #pragma unroll
            for (int i = 0; i < TM; i++) a[i] = As[kk][ty * TM + i];
            #pragma unroll
            for (int j = 0; j < TN; j++) b[j] = Ws[kk][tx * TN + j];
            #pragma unroll
            for (int i = 0; i < TM; i++)
                #pragma unroll
                for (int j = 0; j < TN; j++) acc[i][j] += a[i] * b[j];
        }
    }

    #pragma unroll
    for (int i = 0; i < TM; i++) {
        size_t rbase = (size_t)(m0 + ty * TM + i) * N + n0 + tx * TN;
        #pragma unroll
        for (int j = 0; j < TN; j += 4) {
            float4 v = make_float4(acc[i][j], acc[i][j + 1], acc[i][j + 2], acc[i][j + 3]);
            if (ADD_RES) {
                float4 r = *(const float4*)(Res + rbase + j);
                v.x += r.x; v.y += r.y; v.z += r.z; v.w += r.w;
            }
            *(float4*)(C + rbase + j) = v;
        }
    }
}

// ---------------- causal depthwise conv (K=4) + bias + SiLU -----------------
__global__ void conv_silu_k(const float* __restrict__ cw, const float* __restrict__ cb)
{
    int c = blockIdx.x * 256 + threadIdx.x;   // 0..2047
    int t = blockIdx.y;                       // 0..2047
    int b = blockIdx.z;                       // 0..1
    float4 w = ((const float4*)cw)[c];        // conv_w[c,0,0..3]
    float acc = cb[c];
    size_t colbase = (size_t)b * TT * (2 * DI) + c;
    size_t stride = 2 * DI;
    if (t >= 3) acc += w.x * g_xz[colbase + (size_t)(t - 3) * stride];
    if (t >= 2) acc += w.y * g_xz[colbase + (size_t)(t - 2) * stride];
    if (t >= 1) acc += w.z * g_xz[colbase + (size_t)(t - 1) * stride];
    acc += w.w * g_xz[colbase + (size_t)t * stride];
    float sig = 1.f / (1.f + expf(-acc));
    g_xs[((size_t)b * TT + t) * DI + c] = acc * sig;
}

// ---------------- dt = softplus(xs @ dt_w^T + dt_b) -------------------------
__global__ void dt_k(const float* __restrict__ dtw, const float* __restrict__ dtb)
{
    int row = blockIdx.x;
    int tid = threadIdx.x;
    const float* xr = g_xs + (size_t)row * DI;
    float acc[NH];
    #pragma unroll
    for (int h = 0; h < NH; h++) acc[h] = 0.f;
    for (int k = tid; k < DI; k += 256) {
        float xv = xr[k];
        #pragma unroll
        for (int h = 0; h < NH; h++) acc[h] += xv * dtw[h * DI + k];
    }
    __shared__ float red[NH][256];
    #pragma unroll
    for (int h = 0; h < NH; h++) red[h][tid] = acc[h];
    __syncthreads();
    for (int s = 128; s > 0; s >>= 1) {
        if (tid < s) {
            #pragma unroll
            for (int h = 0; h < NH; h++) red[h][tid] += red[h][tid + s];
        }
        __syncthreads();
    }
    if (tid < NH) {
        float v = red[tid][0] + dtb[tid];
        float sp = (v > 20.f) ? v : log1pf(expf(v));
        g_dt[(size_t)row * NH + tid] = sp;
    }
}

// ---------------- selective scan + D-skip + SiLU(z) gating ------------------
// grid: (d_tile=8, h=8, b=2), 256 threads.
// warp w handles d = dtile*32 + w*4 + (lane&3); lane>>2 = n-group of 8 states.
__global__ void __launch_bounds__(256)
scan_k(const float* __restrict__ A_log, const float* __restrict__ Dp)
{
    int dtile = blockIdx.x;
    int h = blockIdx.y;
    int b = blockIdx.z;
    int warp = threadIdx.x >> 5, lane = threadIdx.x & 31;
    int dl = lane & 3;
    int ng = lane >> 2;                 // 0..7
    int d = dtile * 32 + warp * 4 + dl; // 0..255
    int nbase = ng * 8;

    float A = -expf(A_log[h]);
    float Dh = Dp[h];
    float hs[8];
    #pragma unroll
    for (int j = 0; j < 8; j++) hs[j] = 0.f;

    size_t rb = (size_t)b * TT;
    for (int t = 0; t < TT; t++) {
        size_t row = rb + t;
        float dtv = g_dt[row * NH + h];
        float dA = expf(dtv * A);
        const float* Bp = g_Bm + row * (NH * DS) + h * DS + nbase;
        const float* Cp = g_Cm + row * (NH * DS) + h * DS + nbase;
        float4 b0 = *(const float4*)(Bp);
        float4 b1 = *(const float4*)(Bp + 4);
        float4 c0 = *(const float4*)(Cp);
        float4 c1 = *(const float4*)(Cp + 4);
        float xd = g_xs[row * DI + h * DH + d];
        float dtx = dtv * xd;

        float acc;
        hs[0] = dA * hs[0] + b0.x * dtx; acc  = c0.x * hs[0];
        hs[1] = dA * hs[1] + b0.y * dtx; acc += c0.y * hs[1];
        hs[2] = dA * hs[2] + b0.z * dtx; acc += c0.z * hs[2];
        hs[3] = dA * hs[3] + b0.w * dtx; acc += c0.w * hs[3];
        hs[4] = dA * hs[4] + b1.x * dtx; acc += c1.x * hs[4];
        hs[5] = dA * hs[5] + b1.y * dtx; acc += c1.y * hs[5];
        hs[6] = dA * hs[6] + b1.z * dtx; acc += c1.z * hs[6];
        hs[7] = dA * hs[7] + b1.w * dtx; acc += c1.w * hs[7];

        acc += __shfl_xor_sync(0xffffffffu, acc, 16);
        acc += __shfl_xor_sync(0xffffffffu, acc, 8);
        acc += __shfl_xor_sync(0xffffffffu, acc, 4);

        if (ng == 0) {
            float z = g_xz[row * (2 * DI) + DI + h * DH + d];
            float sig = 1.f / (1.f + __expf(-z));
            g_y[row * DI + h * DH + d] = (acc + Dh * xd) * (z * sig);
        }
    }
}

// ---------------- launch ----------------------------------------------------
extern "C" void kernel_launch(void* const* d_in, const int* in_sizes, int n_in,
                              void* d_out, int out_size)
{
    const float* x      = (const float*)d_in[0];
    const float* norm_w = (const float*)d_in[1];
    const float* in_w   = (const float*)d_in[2];
    const float* conv_w = (const float*)d_in[3];
    const float* conv_b = (const float*)d_in[4];
    const float* A_log  = (const float*)d_in[5];
    const float* B_w    = (const float*)d_in[6];
    const float* C_w    = (const float*)d_in[7];
    const float* dt_w   = (const float*)d_in[8];
    const float* dt_b   = (const float*)d_in[9];
    const float* Dp     = (const float*)d_in[10];
    const float* out_w  = (const float*)d_in[11];
    float* out = (float*)d_out;

    float* g_xn_p; cudaGetSymbolAddress((void**)&g_xn_p, g_xn);
    float* g_xz_p; cudaGetSymbolAddress((void**)&g_xz_p, g_xz);
    float* g_xs_p; cudaGetSymbolAddress((void**)&g_xs_p, g_xs);
    float* g_Bm_p; cudaGetSymbolAddress((void**)&g_Bm_p, g_Bm);
    float* g_Cm_p; cudaGetSymbolAddress((void**)&g_Cm_p, g_Cm);
    float* g_y_p;  cudaGetSymbolAddress((void**)&g_y_p,  g_y);

    // 1. RMSNorm
    rmsnorm_k<<<NROWS, 256>>>(x, norm_w);

    // 2. xz = xn @ in_w^T   (4096 x 4096 x 1024)
    sgemm_nt<false><<<dim3(4096 / 128, NROWS / 128), 256>>>(
        g_xn_p, in_w, g_xz_p, nullptr, NROWS, 2 * DI, DM);

    // 3. causal conv + SiLU on first half of xz
    conv_silu_k<<<dim3(DI / 256, TT, BSZ), 256>>>(conv_w, conv_b);

    // 4. B/C projections (4096 x 512 x 2048 each)
    sgemm_nt<false><<<dim3(512 / 128, NROWS / 128), 256>>>(
        g_xs_p, B_w, g_Bm_p, nullptr, NROWS, NH * DS, DI);
    sgemm_nt<false><<<dim3(512 / 128, NROWS / 128), 256>>>(
        g_xs_p, C_w, g_Cm_p, nullptr, NROWS, NH * DS, DI);

    // 5. dt (skinny GEMM + softplus)
    dt_k<<<NROWS, 256>>>(dt_w, dt_b);

    // 6. selective scan + D skip + gating
    scan_k<<<dim3(8, NH, BSZ), 256>>>(A_log, Dp);

    // 7. out = y @ out_w^T + residual   (4096 x 1024 x 2048)
    sgemm_nt<true><<<dim3(1024 / 128, NROWS / 128), 256>>>(
        g_y_p, out_w, out, x, NROWS, DM, DI);
}

// round 5
// speedup vs baseline: 3.1647x; 3.1647x over previous
#include <cuda_runtime.h>
#include <cuda_bf16.h>
#include <math.h>
#include <stdint.h>

// ---------------- problem constants ----------------------------------------
#define BSZ 2
#define TT 2048
#define DM 1024
#define DI 2048
#define NH 8
#define DS 64
#define DH 256
#define NROWS (BSZ*TT)          // 4096
#define EPSV 1e-6f
#define NCATP 1280              // B(512) | C(512) | dt(8) | pad

// ---------------- scratch (device globals) ---------------------------------
__device__ __nv_bfloat16 g_xn[(size_t)NROWS * DM];
__device__ float         g_xz[(size_t)NROWS * 2 * DI];
__device__ __nv_bfloat16 g_xs[(size_t)NROWS * DI];
__device__ float         g_bcdt[(size_t)NROWS * NCATP];
__device__ float         g_dt[(size_t)NROWS * NH];
__device__ __nv_bfloat16 g_y [(size_t)NROWS * DI];
__device__ __nv_bfloat16 g_inw [(size_t)(2*DI) * DM];
__device__ __nv_bfloat16 g_wcat[(size_t)NCATP * DI];
__device__ __nv_bfloat16 g_outw[(size_t)DM * DI];

// ---------------- PTX helpers ----------------------------------------------
__device__ __forceinline__ uint32_t smem_u32(const void* p) {
    uint32_t a;
    asm("{ .reg .u64 t; cvta.to.shared.u64 t, %1; cvt.u32.u64 %0, t; }" : "=r"(a) : "l"(p));
    return a;
}

#define CP_ASYNC16(dst, src) \
    asm volatile("cp.async.cg.shared.global [%0], [%1], 16;" :: "r"(dst), "l"(src) : "memory")
#define CP_COMMIT() asm volatile("cp.async.commit_group;" ::: "memory")

#define LDM_X4(r0, r1, r2, r3, addr) \
    asm volatile("ldmatrix.sync.aligned.m8n8.x4.shared.b16 {%0,%1,%2,%3}, [%4];" \
                 : "=r"(r0), "=r"(r1), "=r"(r2), "=r"(r3) : "r"(addr))
#define LDM_X2(r0, r1, addr) \
    asm volatile("ldmatrix.sync.aligned.m8n8.x2.shared.b16 {%0,%1}, [%2];" \
                 : "=r"(r0), "=r"(r1) : "r"(addr))

#define MMA16816(d, a0, a1, a2, a3, b0, b1) \
    asm volatile("mma.sync.aligned.m16n8k16.row.col.f32.bf16.bf16.f32 " \
                 "{%0,%1,%2,%3}, {%4,%5,%6,%7}, {%8,%9}, {%0,%1,%2,%3};" \
                 : "+f"((d)[0]), "+f"((d)[1]), "+f"((d)[2]), "+f"((d)[3]) \
                 : "r"(a0), "r"(a1), "r"(a2), "r"(a3), "r"(b0), "r"(b1))

// ---------------- bf16 mma.sync GEMM: C[M,N] = A[M,K] @ W[N,K]^T (+Res) ----
// BM=BN=128, BK=32, 256 threads, 8 warps (2x4), warp tile 64x32.
#define BM 128
#define BN 128
#define BKK 32
#define ROWE 40        // smem row stride in bf16 elements (32 + 8 pad)
#define ROWB 80        // bytes

template <bool ADD_RES>
__global__ void __launch_bounds__(256)
gemm_mma(const __nv_bfloat16* __restrict__ A, const __nv_bfloat16* __restrict__ W,
         float* __restrict__ C, const float* __restrict__ Res,
         int M, int N, int K)
{
    __shared__ __nv_bfloat16 As[2][BM * ROWE];
    __shared__ __nv_bfloat16 Bs[2][BN * ROWE];

    int tid = threadIdx.x;
    int wid = tid >> 5, lane = tid & 31;
    int wm = wid >> 2, wn = wid & 3;         // 2 x 4 warp grid
    int m0 = blockIdx.y * BM;
    int n0 = blockIdx.x * BN;

    const __nv_bfloat16* Ag = A + (size_t)m0 * K;
    const __nv_bfloat16* Wg = W + (size_t)n0 * K;

    uint32_t sA[2] = { smem_u32(As[0]), smem_u32(As[1]) };
    uint32_t sB[2] = { smem_u32(Bs[0]), smem_u32(Bs[1]) };

    float acc[4][4][4];
    #pragma unroll
    for (int i = 0; i < 4; i++)
        #pragma unroll
        for (int j = 0; j < 4; j++)
            #pragma unroll
            for (int f = 0; f < 4; f++) acc[i][j][f] = 0.f;

    int nk = K / BKK;

    // stage 0 load: 512 16B-chunks per operand
    for (int i = tid; i < 512; i += 256) {
        int r = i >> 2, c = i & 3;
        CP_ASYNC16(sA[0] + r * ROWB + c * 16, Ag + (size_t)r * K + c * 8);
        CP_ASYNC16(sB[0] + r * ROWB + c * 16, Wg + (size_t)r * K + c * 8);
    }
    CP_COMMIT();

    int buf = 0;
    for (int kt = 0; kt < nk; kt++) {
        if (kt + 1 < nk) {
            int k0 = (kt + 1) * BKK;
            int nb = buf ^ 1;
            for (int i = tid; i < 512; i += 256) {
                int r = i >> 2, c = i & 3;
                CP_ASYNC16(sA[nb] + r * ROWB + c * 16, Ag + (size_t)r * K + k0 + c * 8);
                CP_ASYNC16(sB[nb] + r * ROWB + c * 16, Wg + (size_t)r * K + k0 + c * 8);
            }
            CP_COMMIT();
            asm volatile("cp.async.wait_group 1;" ::: "memory");
        } else {
            asm volatile("cp.async.wait_group 0;" ::: "memory");
        }
        __syncthreads();

        #pragma unroll
        for (int ks = 0; ks < 2; ks++) {
            uint32_t a[4][4];
            #pragma unroll
            for (int i = 0; i < 4; i++) {
                int row = wm * 64 + i * 16 + (lane & 15);
                int col = ks * 16 + (lane >> 4) * 8;
                LDM_X4(a[i][0], a[i][1], a[i][2], a[i][3],
                       sA[buf] + (uint32_t)(row * ROWB + col * 2));
            }
            uint32_t b[4][2];
            #pragma unroll
            for (int j = 0; j < 4; j++) {
                int row = wn * 32 + j * 8 + (lane & 7);
                int col = ks * 16 + ((lane >> 3) & 1) * 8;
                LDM_X2(b[j][0], b[j][1],
                       sB[buf] + (uint32_t)(row * ROWB + col * 2));
            }
            #pragma unroll
            for (int i = 0; i < 4; i++)
                #pragma unroll
                for (int j = 0; j < 4; j++)
                    MMA16816(acc[i][j], a[i][0], a[i][1], a[i][2], a[i][3],
                             b[j][0], b[j][1]);
        }
        __syncthreads();
        buf ^= 1;
    }

    // epilogue: direct register -> gmem (float2 per c-frag half)
    int gid = lane >> 2, t4 = lane & 3;
    #pragma unroll
    for (int i = 0; i < 4; i++) {
        int row0 = m0 + wm * 64 + i * 16 + gid;
        #pragma unroll
        for (int j = 0; j < 4; j++) {
            int col = n0 + wn * 32 + j * 8 + t4 * 2;
            size_t i0 = (size_t)row0 * N + col;
            size_t i1 = (size_t)(row0 + 8) * N + col;
            float2 v0 = make_float2(acc[i][j][0], acc[i][j][1]);
            float2 v1 = make_float2(acc[i][j][2], acc[i][j][3]);
            if (ADD_RES) {
                float2 r0 = *(const float2*)(Res + i0);
                float2 r1 = *(const float2*)(Res + i1);
                v0.x += r0.x; v0.y += r0.y;
                v1.x += r1.x; v1.y += r1.y;
            }
            *(float2*)(C + i0) = v0;
            *(float2*)(C + i1) = v1;
        }
    }
}

// ---------------- weight conversion ----------------------------------------
__global__ void cvt_bf16_k(const float* __restrict__ in, __nv_bfloat16* __restrict__ out, int n)
{
    for (int i = blockIdx.x * 256 + threadIdx.x; i < n; i += gridDim.x * 256)
        out[i] = __float2bfloat16(in[i]);
}

__global__ void build_wcat_k(const float* __restrict__ Bw, const float* __restrict__ Cw,
                             const float* __restrict__ dtw)
{
    int n = NCATP * DI;
    for (int i = blockIdx.x * 256 + threadIdx.x; i < n; i += gridDim.x * 256) {
        int r = i >> 11, k = i & (DI - 1);
        float v;
        if (r < 512)       v = Bw[(size_t)r * DI + k];
        else if (r < 1024) v = Cw[(size_t)(r - 512) * DI + k];
        else if (r < 1032) v = dtw[(size_t)(r - 1024) * DI + k];
        else               v = 0.f;
        g_wcat[i] = __float2bfloat16(v);
    }
}

// ---------------- RMSNorm (writes bf16) -------------------------------------
__global__ void rmsnorm_k(const float* __restrict__ x, const float* __restrict__ w)
{
    int row = blockIdx.x;
    const float* xr = x + (size_t)row * DM;
    float s = 0.f;
    for (int i = threadIdx.x; i < DM; i += 256) { float v = xr[i]; s += v * v; }
    __shared__ float red[8];
    #pragma unroll
    for (int o = 16; o; o >>= 1) s += __shfl_xor_sync(0xffffffffu, s, o);
    if ((threadIdx.x & 31) == 0) red[threadIdx.x >> 5] = s;
    __syncthreads();
    if (threadIdx.x < 8) {
        float v = red[threadIdx.x];
        #pragma unroll
        for (int o = 4; o; o >>= 1) v += __shfl_xor_sync(0xffu, v, o);
        if (threadIdx.x == 0) red[0] = rsqrtf(v / (float)DM + EPSV);
    }
    __syncthreads();
    float sc = red[0];
    for (int i = threadIdx.x; i < DM; i += 256)
        g_xn[(size_t)row * DM + i] = __float2bfloat16(xr[i] * sc * w[i]);
}

// ---------------- causal depthwise conv (K=4) + bias + SiLU -> bf16 ---------
__global__ void conv_silu_k(const float* __restrict__ cw, const float* __restrict__ cb)
{
    int c = blockIdx.x * 256 + threadIdx.x;
    int t = blockIdx.y;
    int b = blockIdx.z;
    float4 w = ((const float4*)cw)[c];
    float acc = cb[c];
    size_t colbase = (size_t)b * TT * (2 * DI) + c;
    const size_t stride = 2 * DI;
    if (t >= 3) acc += w.x * g_xz[colbase + (size_t)(t - 3) * stride];
    if (t >= 2) acc += w.y * g_xz[colbase + (size_t)(t - 2) * stride];
    if (t >= 1) acc += w.z * g_xz[colbase + (size_t)(t - 1) * stride];
    acc += w.w * g_xz[colbase + (size_t)t * stride];
    float sig = 1.f / (1.f + expf(-acc));
    g_xs[((size_t)b * TT + t) * DI + c] = __float2bfloat16(acc * sig);
}

// ---------------- dt finalize: softplus(raw + bias) -------------------------
__global__ void dt_fin_k(const float* __restrict__ dtb)
{
    int i = blockIdx.x * 256 + threadIdx.x;
    if (i < NROWS * NH) {
        int row = i >> 3, h = i & 7;
        float v = g_bcdt[(size_t)row * NCATP + 1024 + h] + dtb[h];
        g_dt[i] = (v > 20.f) ? v : log1pf(expf(v));
    }
}

// ---------------- selective scan + D-skip + SiLU(z) gating -> bf16 ----------
__global__ void __launch_bounds__(256)
scan_k(const float* __restrict__ A_log, const float* __restrict__ Dp)
{
    int dtile = blockIdx.x;
    int h = blockIdx.y;
    int b = blockIdx.z;
    int warp = threadIdx.x >> 5, lane = threadIdx.x & 31;
    int dl = lane & 3;
    int ng = lane >> 2;
    int d = dtile * 32 + warp * 4 + dl;
    int nbase = ng * 8;

    float A = -expf(A_log[h]);
    float Dh = Dp[h];
    float hs[8];
    #pragma unroll
    for (int j = 0; j < 8; j++) hs[j] = 0.f;

    size_t rb = (size_t)b * TT;
    size_t bcoff = (size_t)h * DS + nbase;
    size_t ccoff = 512 + bcoff;
    int xoff = h * DH + d;

    size_t row = rb;
    float dtv = g_dt[row * NH + h];
    const float* Bp = g_bcdt + row * NCATP + bcoff;
    const float* Cp = g_bcdt + row * NCATP + ccoff;
    float4 b0 = *(const float4*)(Bp);
    float4 b1 = *(const float4*)(Bp + 4);
    float4 c0 = *(const float4*)(Cp);
    float4 c1 = *(const float4*)(Cp + 4);
    float xd = __bfloat162float(g_xs[row * DI + xoff]);
    float zv = (ng == 0) ? g_xz[row * (2 * DI) + DI + xoff] : 0.f;

    for (int t = 0; t < TT; t++) {
        float n_dt = 0.f, n_xd = 0.f, n_zv = 0.f;
        float4 nb0 = b0, nb1 = b1, nc0 = c0, nc1 = c1;
        if (t + 1 < TT) {
            size_t nrow = rb + t + 1;
            n_dt = g_dt[nrow * NH + h];
            const float* nBp = g_bcdt + nrow * NCATP + bcoff;
            const float* nCp = g_bcdt + nrow * NCATP + ccoff;
            nb0 = *(const float4*)(nBp);
            nb1 = *(const float4*)(nBp + 4);
            nc0 = *(const float4*)(nCp);
            nc1 = *(const float4*)(nCp + 4);
            n_xd = __bfloat162float(g_xs[nrow * DI + xoff]);
            if (ng == 0) n_zv = g_xz[nrow * (2 * DI) + DI + xoff];
        }

        float dA = expf(dtv * A);
        float dtx = dtv * xd;
        float acc;
        hs[0] = dA * hs[0] + b0.x * dtx; acc  = c0.x * hs[0];
        hs[1] = dA * hs[1] + b0.y * dtx; acc += c0.y * hs[1];
        hs[2] = dA * hs[2] + b0.z * dtx; acc += c0.z * hs[2];
        hs[3] = dA * hs[3] + b0.w * dtx; acc += c0.w * hs[3];
        hs[4] = dA * hs[4] + b1.x * dtx; acc += c1.x * hs[4];
        hs[5] = dA * hs[5] + b1.y * dtx; acc += c1.y * hs[5];
        hs[6] = dA * hs[6] + b1.z * dtx; acc += c1.z * hs[6];
        hs[7] = dA * hs[7] + b1.w * dtx; acc += c1.w * hs[7];

        acc += __shfl_xor_sync(0xffffffffu, acc, 16);
        acc += __shfl_xor_sync(0xffffffffu, acc, 8);
        acc += __shfl_xor_sync(0xffffffffu, acc, 4);

        if (ng == 0) {
            float sig = 1.f / (1.f + __expf(-zv));
            g_y[(rb + t) * DI + xoff] = __float2bfloat16((acc + Dh * xd) * (zv * sig));
        }

        dtv = n_dt; xd = n_xd; zv = n_zv;
        b0 = nb0; b1 = nb1; c0 = nc0; c1 = nc1;
    }
}

// ---------------- launch ----------------------------------------------------
extern "C" void kernel_launch(void* const* d_in, const int* in_sizes, int n_in,
                              void* d_out, int out_size)
{
    const float* x      = (const float*)d_in[0];
    const float* norm_w = (const float*)d_in[1];
    const float* in_w   = (const float*)d_in[2];
    const float* conv_w = (const float*)d_in[3];
    const float* conv_b = (const float*)d_in[4];
    const float* A_log  = (const float*)d_in[5];
    const float* B_w    = (const float*)d_in[6];
    const float* C_w    = (const float*)d_in[7];
    const float* dt_w   = (const float*)d_in[8];
    const float* dt_b   = (const float*)d_in[9];
    const float* Dp     = (const float*)d_in[10];
    const float* out_w  = (const float*)d_in[11];
    float* out = (float*)d_out;

    __nv_bfloat16 *p_xn, *p_xs, *p_y, *p_inw, *p_wcat, *p_outw;
    float *p_xz, *p_bcdt;
    cudaGetSymbolAddress((void**)&p_xn, g_xn);
    cudaGetSymbolAddress((void**)&p_xz, g_xz);
    cudaGetSymbolAddress((void**)&p_xs, g_xs);
    cudaGetSymbolAddress((void**)&p_bcdt, g_bcdt);
    cudaGetSymbolAddress((void**)&p_y, g_y);
    cudaGetSymbolAddress((void**)&p_inw, g_inw);
    cudaGetSymbolAddress((void**)&p_wcat, g_wcat);
    cudaGetSymbolAddress((void**)&p_outw, g_outw);

    // weight conversions (bf16)
    cvt_bf16_k<<<256, 256>>>(in_w, p_inw, 2 * DI * DM);
    cvt_bf16_k<<<256, 256>>>(out_w, p_outw, DM * DI);
    build_wcat_k<<<256, 256>>>(B_w, C_w, dt_w);

    // 1. RMSNorm -> bf16
    rmsnorm_k<<<NROWS, 256>>>(x, norm_w);

    // 2. xz = xn @ in_w^T   (4096 x 4096 x 1024)
    gemm_mma<false><<<dim3(4096 / BN, NROWS / BM), 256>>>(
        p_xn, p_inw, p_xz, nullptr, NROWS, 2 * DI, DM);

    // 3. causal conv + SiLU -> bf16
    conv_silu_k<<<dim3(DI / 256, TT, BSZ), 256>>>(conv_w, conv_b);

    // 4. [B | C | dt] = xs @ wcat^T   (4096 x 1280 x 2048)
    gemm_mma<false><<<dim3(NCATP / BN, NROWS / BM), 256>>>(
        p_xs, p_wcat, p_bcdt, nullptr, NROWS, NCATP, DI);

    // 5. dt softplus
    dt_fin_k<<<(NROWS * NH + 255) / 256, 256>>>(dt_b);

    // 6. selective scan + gating -> bf16
    scan_k<<<dim3(8, NH, BSZ), 256>>>(A_log, Dp);

    // 7. out = y @ out_w^T + residual   (4096 x 1024 x 2048)
    gemm_mma<true><<<dim3(1024 / BN, NROWS / BM), 256>>>(
        p_y, p_outw, out, x, NROWS, DM, DI);
}